// round 6
// baseline (speedup 1.0000x reference)
#include <cuda_runtime.h>
#include <cstdint>

#define NB 4
#define NX 64
#define NY 64
#define NZ 40
#define C  32
#define KM 16
#define KZM 16
#define KYM 32

// ================= compile-time trig ======
constexpr double D_PI = 3.141592653589793238462643383279502884;

constexpr double tsin_(double x) {
    double x2 = x * x, t = x, s = x;
    for (int n = 1; n <= 13; n++) { t *= -x2 / ((2.0*n) * (2.0*n + 1.0)); s += t; }
    return s;
}
constexpr double tcos_(double x) {
    double x2 = x * x, t = 1.0, s = 1.0;
    for (int n = 1; n <= 13; n++) { t *= -x2 / ((2.0*n - 1.0) * (2.0*n)); s += t; }
    return s;
}
constexpr double ang_(int m, int N) {
    int mm = m % N;
    if (mm > N / 2) mm -= N;
    return 2.0 * D_PI * mm / N;
}

struct FXT { float c[16][64]; float s[16][64]; };
constexpr FXT mkFX() {
    FXT t{};
    for (int k = 0; k < 16; k++)
        for (int n = 0; n < 64; n++) {
            double a = ang_(k * n, 64);
            t.c[k][n] = (float)tcos_(a);
            t.s[k][n] = (float)(-tsin_(a));
        }
    return t;
}
__device__ constexpr FXT FX = mkFX();

struct FZT { float c[16][40]; float s[16][40]; };
constexpr FZT mkFZ() {
    FZT t{};
    for (int k = 0; k < 16; k++) {
        int f = (k < 8) ? k : k + 5;
        for (int n = 0; n < 40; n++) {
            double a = ang_(f * n, 40);
            t.c[k][n] = (float)tcos_(a);
            t.s[k][n] = (float)(-tsin_(a));
        }
    }
    return t;
}
__device__ constexpr FZT FZ = mkFZ();

struct FYT { float c[32][64]; float s[32][64]; };
constexpr FYT mkFY() {
    FYT t{};
    for (int k = 0; k < 32; k++) {
        int f = (k < 16) ? k : k + 1;
        for (int n = 0; n < 64; n++) {
            double a = ang_(f * n, 64);
            t.c[k][n] = (float)tcos_(a);
            t.s[k][n] = (float)(-tsin_(a));
        }
    }
    return t;
}
__device__ constexpr FYT FY = mkFY();

struct IXT { float c[16][64]; float s[16][64]; };
constexpr IXT mkIX() {
    IXT t{};
    for (int k = 0; k < 16; k++)
        for (int n = 0; n < 64; n++) {
            double a = ang_(k * n, 64);
            t.c[k][n] = (float)(tcos_(a) / 64.0);
            t.s[k][n] = (float)(tsin_(a) / 64.0);
        }
    return t;
}
__device__ constexpr IXT IX = mkIX();

// inverse z table, transposed for runtime-z loads: [z][kz]
struct IZT { float c[40][16]; float s[40][16]; };
constexpr IZT mkIZ() {
    IZT t{};
    for (int k = 0; k < 16; k++) {
        int f = (k < 8) ? k : k + 5;
        double w = (f == 0 || f == 20) ? 1.0 : 2.0;
        for (int n = 0; n < 40; n++) {
            double a = ang_(f * n, 40);
            t.c[n][k] = (float)(tcos_(a) * w / 40.0);
            t.s[n][k] = (float)(tsin_(a) * w / 40.0);
        }
    }
    return t;
}
__device__ constexpr IZT IZ = mkIZ();

// inverse y real-axis table: [y][ky]
struct IYT { float c[64][32]; float s[64][32]; };
constexpr IYT mkIY() {
    IYT t{};
    for (int k = 0; k < 32; k++) {
        int f = (k < 16) ? k : k + 1;
        double w = (f == 0 || f == 32) ? 1.0 : 2.0;
        for (int n = 0; n < 64; n++) {
            double a = ang_(f * n, 64);
            t.c[n][k] = (float)(tcos_(a) * w / 64.0);
            t.s[n][k] = (float)(tsin_(a) * w / 64.0);
        }
    }
    return t;
}
__device__ constexpr IYT IY = mkIY();

// ================= scratch =================
__device__ float2 g_Qx[(size_t)NB*KM*NY*NZ*C];    // [b][kx][y][z][i]
__device__ float2 g_P1[(size_t)NB*NX*NY*KZM*C];   // [b][x][y][kz][i]
__device__ float2 g_F [(size_t)512*160*C];        // [mode][row][c]
__device__ float  g_acc[(size_t)NB*NX*NY*NZ*C];   // [b][x][y][z][o]

// ================= 1x1 conv (init acc) =================
__global__ void __launch_bounds__(640) k_conv(const float* __restrict__ x,
                                              const float* __restrict__ w,
                                              const float* __restrict__ bias) {
    __shared__ float xs[NZ*C];
    __shared__ float Wt[C*C];
    __shared__ float bs[C];
    int y = blockIdx.x, xx = blockIdx.y, b = blockIdx.z;
    int tid = threadIdx.x;
    const float* xr = x + (((size_t)(b*NX+xx)*NY + y) * NZ) * C;
    for (int t = tid; t < NZ*C; t += 640) xs[t] = xr[t];
    for (int t = tid; t < C*C;  t += 640) Wt[t] = w[(t % C) * C + (t / C)];
    if (tid < C) bs[tid] = bias[tid];
    __syncthreads();
    int o = tid & 31, zz = tid >> 5;
    float* ar = g_acc + (((size_t)(b*NX+xx)*NY + y) * NZ) * C;
    for (int rep = 0; rep < 2; rep++) {
        int z = zz + rep * 20;
        float v = bs[o];
        #pragma unroll
        for (int i = 0; i < C; i++) v += xs[z*C + i] * Wt[i*C + o];
        ar[z*C + o] = v;
    }
}

// ================= forward x DFT (all 16 modes) ============================
__global__ void __launch_bounds__(256) k_fftx16(const float* __restrict__ x) {
    int w = threadIdx.x >> 5, i = threadIdx.x & 31;
    int z = blockIdx.x * 8 + w;
    int y = blockIdx.y, b = blockIdx.z;
    const float* px = x + (((size_t)b*NX*NY + y)*NZ + z)*C + i;
    float2 acc[16];
    #pragma unroll
    for (int k = 0; k < 16; k++) acc[k] = make_float2(0.f, 0.f);
    #pragma unroll
    for (int xx = 0; xx < NX; xx++) {
        float v = px[(size_t)xx*NY*NZ*C];
        #pragma unroll
        for (int k = 0; k < 16; k++) {
            acc[k].x = fmaf(v, FX.c[k][xx], acc[k].x);
            acc[k].y = fmaf(v, FX.s[k][xx], acc[k].y);
        }
    }
    #pragma unroll
    for (int k = 0; k < 16; k++)
        g_Qx[((((size_t)b*KM + k)*NY + y)*NZ + z)*C + i] = acc[k];
}

// ================= forward z rDFT (16 modes) ================================
__global__ void __launch_bounds__(256) k_rfftz(const float* __restrict__ x) {
    int w = threadIdx.x >> 5, i = threadIdx.x & 31;
    int y = blockIdx.x * 8 + w;
    int xx = blockIdx.y, b = blockIdx.z;
    const float* px = x + (((size_t)(b*NX+xx)*NY + y) * NZ) * C + i;
    float2 acc[16];
    #pragma unroll
    for (int k = 0; k < 16; k++) acc[k] = make_float2(0.f, 0.f);
    #pragma unroll
    for (int z = 0; z < NZ; z++) {
        float v = px[(size_t)z*C];
        #pragma unroll
        for (int k = 0; k < 16; k++) {
            acc[k].x = fmaf(v, FZ.c[k][z], acc[k].x);
            acc[k].y = fmaf(v, FZ.s[k][z], acc[k].y);
        }
    }
    float2* q = g_P1 + (((size_t)(b*NX+xx)*NY + y) * KZM) * C + i;
    #pragma unroll
    for (int k = 0; k < 16; k++) q[(size_t)k*C] = acc[k];
}

// ================= xz: z DFT of Qx (all 16 kz modes) ========================
__global__ void __launch_bounds__(256) k_zfftQ16() {
    int w = threadIdx.x >> 5, i = threadIdx.x & 31;
    int y = blockIdx.x * 8 + w;
    int kx = blockIdx.y, b = blockIdx.z;
    const float2* q = g_Qx + (((size_t)(b*KM+kx)*NY + y) * NZ) * C + i;
    float2 acc[16];
    #pragma unroll
    for (int k = 0; k < 16; k++) acc[k] = make_float2(0.f, 0.f);
    #pragma unroll
    for (int z = 0; z < NZ; z++) {
        float2 a = q[(size_t)z*C];
        #pragma unroll
        for (int k = 0; k < 16; k++) {
            float cc = FZ.c[k][z], ss = FZ.s[k][z];
            acc[k].x = fmaf(a.x, cc, acc[k].x);
            acc[k].x = fmaf(a.y, -ss, acc[k].x);
            acc[k].y = fmaf(a.x, ss, acc[k].y);
            acc[k].y = fmaf(a.y, cc, acc[k].y);
        }
    }
    #pragma unroll
    for (int k = 0; k < 16; k++) {
        int m = kx*KZM + k;
        g_F[((size_t)m*(NB*NY) + b*NY + y)*C + i] = acc[k];
    }
}

// ================= xy: y DFT (real axis, 16 of 32 modes from M0) ============
template<int M0>
__global__ void __launch_bounds__(256) k_yfftQ16() {
    int w = threadIdx.x >> 5, i = threadIdx.x & 31;
    int z = blockIdx.x * 8 + w;
    int kx = blockIdx.y, b = blockIdx.z;
    const float2* q = g_Qx + (((size_t)(b*KM+kx)*NY) * NZ + z) * C + i;
    float2 acc[16];
    #pragma unroll
    for (int k = 0; k < 16; k++) acc[k] = make_float2(0.f, 0.f);
    #pragma unroll
    for (int y = 0; y < NY; y++) {
        float2 a = q[(size_t)y*NZ*C];
        #pragma unroll
        for (int k = 0; k < 16; k++) {
            float cc = FY.c[M0+k][y], ss = FY.s[M0+k][y];
            acc[k].x = fmaf(a.x, cc, acc[k].x);
            acc[k].x = fmaf(a.y, -ss, acc[k].x);
            acc[k].y = fmaf(a.x, ss, acc[k].y);
            acc[k].y = fmaf(a.y, cc, acc[k].y);
        }
    }
    #pragma unroll
    for (int k = 0; k < 16; k++) {
        int m = kx*KYM + M0 + k;
        g_F[((size_t)m*(NB*NZ) + b*NZ + z)*C + i] = acc[k];
    }
}

// ================= yz: y DFT of P1 (all 16 complex modes) ===================
__global__ void __launch_bounds__(256) k_yfftP16() {
    int w = threadIdx.x >> 5, i = threadIdx.x & 31;
    int kz = blockIdx.x * 8 + w;
    int xx = blockIdx.y, b = blockIdx.z;
    const float2* p = g_P1 + (((size_t)(b*NX+xx)*NY) * KZM + kz) * C + i;
    float2 acc[16];
    #pragma unroll
    for (int k = 0; k < 16; k++) acc[k] = make_float2(0.f, 0.f);
    #pragma unroll
    for (int y = 0; y < NY; y++) {
        float2 a = p[(size_t)y*KZM*C];
        #pragma unroll
        for (int k = 0; k < 16; k++) {
            float cc = FX.c[k][y], ss = FX.s[k][y];
            acc[k].x = fmaf(a.x, cc, acc[k].x);
            acc[k].x = fmaf(a.y, -ss, acc[k].x);
            acc[k].y = fmaf(a.x, ss, acc[k].y);
            acc[k].y = fmaf(a.y, cc, acc[k].y);
        }
    }
    #pragma unroll
    for (int k = 0; k < 16; k++) {
        int m = k*KZM + kz;
        g_F[((size_t)m*(NB*NX) + b*NX + xx)*C + i] = acc[k];
    }
}

// ================= per-mode complex 32x32 channel mix (in place) ============
__global__ void __launch_bounds__(1024) k_mix(const float* __restrict__ fw,
                                              const float* __restrict__ fw2,
                                              int rows, int D) {
    __shared__ float2 Ws[C*C];
    __shared__ float2 Fs[32*C];
    int m = blockIdx.x;
    int tid = threadIdx.x;
    int mpx = 2 * D;
    int kx = m / mpx, km = m % mpx;
    const float* W = (km < D) ? fw : fw2;
    int kk = (km < D) ? km : km - D;
    {
        int i = tid >> 5, o = tid & 31;
        size_t base = ((((size_t)i*C + o)*KM + kx)*D + kk) * 2;
        Ws[i*C + o] = make_float2(W[base], W[base + 1]);
    }
    __syncthreads();
    int o = tid & 31, rr = tid >> 5;
    int nch = rows / 32;
    for (int ch = 0; ch < nch; ch++) {
        size_t idx = ((size_t)m*rows + ch*32 + rr)*C + o;
        Fs[rr*C + o] = g_F[idx];
        __syncthreads();
        float re = 0.f, im = 0.f;
        #pragma unroll
        for (int i = 0; i < C; i++) {
            float2 a = Fs[rr*C + i];
            float2 w = Ws[i*C + o];
            re += a.x*w.x - a.y*w.y;
            im += a.x*w.y + a.y*w.x;
        }
        __syncthreads();
        g_F[idx] = make_float2(re, im);
    }
}

// ================= fused inverse: xz (z-inverse then x-inverse, += acc) =====
__global__ void __launch_bounds__(320) k_invXZ() {
    int w = threadIdx.x >> 5, o = threadIdx.x & 31;
    int u = blockIdx.x, b = blockIdx.y;   // u = y
    const float2* Fb = g_F + ((size_t)b*NY + u)*C + o;   // mode stride NB*NY*C
    for (int zi = 0; zi < 4; zi++) {
        int z = w + zi*10;
        float2 r[16];
        #pragma unroll
        for (int kc = 0; kc < 16; kc++) {
            float re = 0.f, im = 0.f;
            #pragma unroll
            for (int kz = 0; kz < 16; kz++) {
                float2 g = Fb[(size_t)(kc*KZM + kz)*(NB*NY)*C];
                float cc = IZ.c[z][kz], ss = IZ.s[z][kz];
                re = fmaf(g.x, cc, re); re = fmaf(g.y, -ss, re);
                im = fmaf(g.x, ss, im); im = fmaf(g.y, cc, im);
            }
            r[kc] = make_float2(re, im);
        }
        float* ab = g_acc + (((size_t)b*NX*NY + u)*NZ + z)*C + o;
        #pragma unroll
        for (int xc = 0; xc < 8; xc++) {
            float s[8];
            #pragma unroll
            for (int xi = 0; xi < 8; xi++) s[xi] = 0.f;
            #pragma unroll
            for (int kc = 0; kc < 16; kc++) {
                #pragma unroll
                for (int xi = 0; xi < 8; xi++) {
                    s[xi] = fmaf(r[kc].x, IX.c[kc][xc*8+xi], s[xi]);
                    s[xi] = fmaf(r[kc].y, -IX.s[kc][xc*8+xi], s[xi]);
                }
            }
            #pragma unroll
            for (int xi = 0; xi < 8; xi++)
                ab[(size_t)(xc*8+xi)*NY*NZ*C] += s[xi];
        }
    }
}

// ================= fused inverse: yz (z-inverse then y-inverse, += acc) =====
__global__ void __launch_bounds__(320) k_invYZ() {
    int w = threadIdx.x >> 5, o = threadIdx.x & 31;
    int xx = blockIdx.x, b = blockIdx.y;
    const float2* Fb = g_F + ((size_t)b*NX + xx)*C + o;  // mode stride NB*NX*C
    for (int zi = 0; zi < 4; zi++) {
        int z = w + zi*10;
        float2 r[16];
        #pragma unroll
        for (int kc = 0; kc < 16; kc++) {
            float re = 0.f, im = 0.f;
            #pragma unroll
            for (int kz = 0; kz < 16; kz++) {
                float2 g = Fb[(size_t)(kc*KZM + kz)*(NB*NX)*C];
                float cc = IZ.c[z][kz], ss = IZ.s[z][kz];
                re = fmaf(g.x, cc, re); re = fmaf(g.y, -ss, re);
                im = fmaf(g.x, ss, im); im = fmaf(g.y, cc, im);
            }
            r[kc] = make_float2(re, im);
        }
        float* ab = g_acc + (((size_t)(b*NX + xx)*NY)*NZ + z)*C + o;  // y stride NZ*C
        #pragma unroll
        for (int yc = 0; yc < 8; yc++) {
            float s[8];
            #pragma unroll
            for (int yi = 0; yi < 8; yi++) s[yi] = 0.f;
            #pragma unroll
            for (int kc = 0; kc < 16; kc++) {
                #pragma unroll
                for (int yi = 0; yi < 8; yi++) {
                    s[yi] = fmaf(r[kc].x, IX.c[kc][yc*8+yi], s[yi]);
                    s[yi] = fmaf(r[kc].y, -IX.s[kc][yc*8+yi], s[yi]);
                }
            }
            #pragma unroll
            for (int yi = 0; yi < 8; yi++)
                ab[(size_t)(yc*8+yi)*NZ*C] += s[yi];
        }
    }
}

// ================= fused inverse: xy (y-inverse then x-inverse, += acc) =====
__global__ void __launch_bounds__(512) k_invXY() {
    int w = threadIdx.x >> 5, o = threadIdx.x & 31;
    int z = blockIdx.x, b = blockIdx.y;
    const float2* Fb = g_F + ((size_t)b*NZ + z)*C + o;   // mode stride NB*NZ*C
    for (int yi = 0; yi < 4; yi++) {
        int y = w + yi*16;
        float2 r[16];
        #pragma unroll
        for (int kx = 0; kx < 16; kx++) r[kx] = make_float2(0.f, 0.f);
        #pragma unroll 4
        for (int ky = 0; ky < 32; ky++) {
            float tyc = IY.c[y][ky], tys = IY.s[y][ky];
            #pragma unroll
            for (int kx = 0; kx < 16; kx++) {
                float2 g = Fb[(size_t)(kx*KYM + ky)*(NB*NZ)*C];
                r[kx].x = fmaf(g.x, tyc, r[kx].x);
                r[kx].x = fmaf(g.y, -tys, r[kx].x);
                r[kx].y = fmaf(g.x, tys, r[kx].y);
                r[kx].y = fmaf(g.y, tyc, r[kx].y);
            }
        }
        float* ab = g_acc + (((size_t)b*NX*NY + y)*NZ + z)*C + o;  // x stride NY*NZ*C
        #pragma unroll
        for (int xc = 0; xc < 8; xc++) {
            float s[8];
            #pragma unroll
            for (int xi = 0; xi < 8; xi++) s[xi] = 0.f;
            #pragma unroll
            for (int kx = 0; kx < 16; kx++) {
                #pragma unroll
                for (int xi = 0; xi < 8; xi++) {
                    s[xi] = fmaf(r[kx].x, IX.c[kx][xc*8+xi], s[xi]);
                    s[xi] = fmaf(r[kx].y, -IX.s[kx][xc*8+xi], s[xi]);
                }
            }
            #pragma unroll
            for (int xi = 0; xi < 8; xi++)
                ab[(size_t)(xc*8+xi)*NY*NZ*C] += s[xi];
        }
    }
}

// ================= feedforward =================
__global__ void __launch_bounds__(256) k_ff(const float* __restrict__ w0,
                                            const float* __restrict__ b0,
                                            const float* __restrict__ w1,
                                            const float* __restrict__ b1,
                                            float* __restrict__ out) {
    __shared__ float w0t[C*64];
    __shared__ float w1t[64*C];
    __shared__ float b0s[64], b1s[C];
    __shared__ float as[8][C];
    __shared__ float h1s[8][64];
    int tid = threadIdx.x;
    for (int t = tid; t < C*64; t += 256) { int i = t / 64, h = t % 64; w0t[t] = w0[h*C + i]; }
    for (int t = tid; t < 64*C; t += 256) { int h = t / C,  o = t % C;  w1t[t] = w1[o*64 + h]; }
    if (tid < 64) b0s[tid] = b0[tid];
    if (tid < C)  b1s[tid] = b1[tid];
    __syncthreads();
    int lane = tid & 31, w = tid >> 5;
    const int TPW = 32;
    size_t t0 = ((size_t)blockIdx.x * 8 + w) * TPW;
    for (int j = 0; j < TPW; j++) {
        size_t t = t0 + j;
        as[w][lane] = g_acc[t*C + lane];
        __syncwarp();
        float h1a = b0s[lane], h1b = b0s[lane + 32];
        #pragma unroll
        for (int i = 0; i < C; i++) {
            float a = as[w][i];
            h1a += a * w0t[i*64 + lane];
            h1b += a * w0t[i*64 + lane + 32];
        }
        h1a = fmaxf(h1a, 0.f); h1b = fmaxf(h1b, 0.f);
        h1s[w][lane] = h1a; h1s[w][lane + 32] = h1b;
        __syncwarp();
        float v = b1s[lane];
        #pragma unroll
        for (int h = 0; h < 64; h++) v += h1s[w][h] * w1t[h*C + lane];
        out[t*C + lane] = v;
        __syncwarp();
    }
}

extern "C" void kernel_launch(void* const* d_in, const int* in_sizes, int n_in,
                              void* d_out, int out_size) {
    const float* x      = (const float*)d_in[0];
    const float* w      = (const float*)d_in[1];
    const float* wb     = (const float*)d_in[2];
    const float* fw_xy  = (const float*)d_in[3];
    const float* fw_yz  = (const float*)d_in[4];
    const float* fw_xz  = (const float*)d_in[5];
    const float* fw2_xy = (const float*)d_in[6];
    const float* fw2_yz = (const float*)d_in[7];
    const float* fw2_xz = (const float*)d_in[8];
    const float* ffw0   = (const float*)d_in[9];
    const float* ffb0   = (const float*)d_in[10];
    const float* ffw1   = (const float*)d_in[11];
    const float* ffb1   = (const float*)d_in[12];
    float* out = (float*)d_out;

    k_conv<<<dim3(NY, NX, NB), 640>>>(x, w, wb);

    // shared forward x-DFT (feeds xz + xy)
    k_fftx16<<<dim3(5, NY, NB), 256>>>(x);

    // ---- xz branch ----
    k_zfftQ16<<<dim3(8, KM, NB), 256>>>();
    k_mix<<<256, 1024>>>(fw_xz, fw2_xz, NB*NY, 8);
    k_invXZ<<<dim3(NY, NB), 320>>>();

    // ---- xy branch ----
    k_yfftQ16<0 ><<<dim3(5, KM, NB), 256>>>();
    k_yfftQ16<16><<<dim3(5, KM, NB), 256>>>();
    k_mix<<<512, 1024>>>(fw_xy, fw2_xy, NB*NZ, 16);
    k_invXY<<<dim3(NZ, NB), 512>>>();

    // ---- yz branch ----
    k_rfftz<<<dim3(8, NX, NB), 256>>>(x);
    k_yfftP16<<<dim3(2, NX, NB), 256>>>();
    k_mix<<<256, 1024>>>(fw_yz, fw2_yz, NB*NX, 8);
    k_invYZ<<<dim3(NX, NB), 320>>>();

    // ---- feedforward ----
    k_ff<<<2560, 256>>>(ffw0, ffb0, ffw1, ffb1, out);
}